// round 9
// baseline (speedup 1.0000x reference)
#include <cuda_runtime.h>
#include <math.h>
#include <stdint.h>

#define T_SEQ 4096
#define DIM   2048
#define NH    16
#define HD    128
#define GK    2048

// ---------------- scratch (no allocations allowed) ----------------
__device__ float g_q[T_SEQ * DIM];
__device__ float g_k[T_SEQ * DIM];
__device__ float g_v[T_SEQ * DIM];
__device__ float g_o[T_SEQ * DIM];       // flash output, k-permuted + rounded
__device__ float g_kp[T_SEQ * DIM];      // K rounded, d-permuted (key-major)
__device__ float g_vt[DIM * T_SEQ];      // V rounded, [h][d][t'], t' key-permuted
__device__ float g_xr[T_SEQ * DIM];      // x rounded + k-permuted
__device__ float g_w[4 * DIM * DIM];     // Wt[N,K] rounded + k-permuted, 4 slabs

// =================== helpers ===================
__device__ __forceinline__ uint32_t smem_u32(const void* p) {
    uint32_t a;
    asm("{ .reg .u64 t; cvta.to.shared.u64 t, %1; cvt.u32.u64 %0, t; }" : "=r"(a) : "l"(p));
    return a;
}
__device__ __forceinline__ uint32_t tf32b(float x) {
    uint32_t r;
    asm("cvt.rna.tf32.f32 %0, %1;" : "=r"(r) : "f"(x));
    return r;
}
__device__ __forceinline__ float tf32f(float x) { return __uint_as_float(tf32b(x)); }
__device__ __forceinline__ void cpa16(uint32_t saddr, const void* g) {
    asm volatile("cp.async.cg.shared.global [%0], [%1], 16;" :: "r"(saddr), "l"(g));
}
__device__ __forceinline__ void mma8(float* d, const uint32_t* a, uint32_t b0, uint32_t b1) {
    asm volatile(
        "mma.sync.aligned.m16n8k8.row.col.f32.tf32.tf32.f32 "
        "{%0,%1,%2,%3}, {%4,%5,%6,%7}, {%8,%9}, {%0,%1,%2,%3};"
        : "+f"(d[0]), "+f"(d[1]), "+f"(d[2]), "+f"(d[3])
        : "r"(a[0]), "r"(a[1]), "r"(a[2]), "r"(a[3]), "r"(b0), "r"(b1));
}

// =================== permute k within 8-groups + round (src = unpermuted) ===================
// dst[c'] = round(src[(c'&~7) + ((c'&7)>>1) + ((c'&1)<<2)])
__global__ __launch_bounds__(256) void permute_k(const float* __restrict__ S,
                                                 float* __restrict__ D)
{
    int idx = blockIdx.x * 256 + threadIdx.x;
    int t = idx >> 11;
    int c = idx & 2047;
    int r = c & 7;
    int src = (c & ~7) + (r >> 1) + ((r & 1) << 2);
    D[idx] = tf32f(S[(size_t)t * DIM + src]);
}

// =================== transpose W[K,N] -> Wt[N,K] with k-permutation + rounding ===================
__global__ __launch_bounds__(256) void transpose_w(const float* __restrict__ W0,
                                                   const float* __restrict__ W1,
                                                   const float* __restrict__ W2,
                                                   const float* __restrict__ W3,
                                                   float* __restrict__ Wt)
{
    __shared__ float t[32][33];
    const int z = blockIdx.z;
    const float* W = (z == 0) ? W0 : (z == 1) ? W1 : (z == 2) ? W2 : W3;
    float* D = Wt + (size_t)z * DIM * DIM;
    const int k0 = blockIdx.x * 32;
    const int n0 = blockIdx.y * 32;
    const int tx = threadIdx.x & 31, ty = threadIdx.x >> 5;
#pragma unroll
    for (int i = 0; i < 4; i++)
        t[ty + 8 * i][tx] = W[(size_t)(k0 + ty + 8 * i) * DIM + n0 + tx];
    __syncthreads();
    const int ksrc = (tx & ~7) + ((tx & 7) >> 1) + ((tx & 1) << 2);
#pragma unroll
    for (int i = 0; i < 4; i++)
        D[(size_t)(n0 + ty + 8 * i) * GK + k0 + tx] = tf32f(t[ksrc][ty + 8 * i]);
}

// =================== mma.sync tf32 GEMM (BK=32, both operands K-major k-permuted) ===================
#define BK        32
#define NSTG      3
#define A_ROWB    144                 // 36 floats (32 + 4 pad)
#define B_ROWB    144
#define A_BYTES   (128 * A_ROWB)      // 18432
#define B_BYTES   (128 * B_ROWB)      // 18432
#define STG_BYTES (A_BYTES + B_BYTES) // 36864
#define NT        (GK / BK)           // 64

__device__ __forceinline__ void load_stage(uint32_t sb, const float* __restrict__ A,
                                           const float* __restrict__ Wt,
                                           int m0, int n0, int kt, int tid) {
    uint32_t st = sb + (uint32_t)(kt % NSTG) * STG_BYTES;
    const int k0 = kt * BK;
#pragma unroll
    for (int i = 0; i < 4; i++) {
        int id = tid + i * 256;            // A: 128 rows x 8 chunks
        int row = id >> 3, seg = id & 7;
        cpa16(st + row * A_ROWB + seg * 16,
              A + (size_t)(m0 + row) * GK + k0 + seg * 4);
    }
#pragma unroll
    for (int i = 0; i < 4; i++) {
        int id = tid + i * 256;            // B: 128 n-rows x 8 chunks
        int row = id >> 3, seg = id & 7;
        cpa16(st + A_BYTES + row * B_ROWB + seg * 16,
              Wt + (size_t)(n0 + row) * GK + k0 + seg * 4);
    }
}

__global__ __launch_bounds__(256, 2) void gemm_mma(const float* __restrict__ A,
                                                   const float* __restrict__ Wr,
                                                   const float* __restrict__ b0p,
                                                   const float* __restrict__ b1p,
                                                   const float* __restrict__ b2p,
                                                   float* __restrict__ C0,
                                                   float* __restrict__ C1,
                                                   float* __restrict__ C2)
{
    extern __shared__ __align__(16) char smem[];
    const uint32_t sb = smem_u32(smem);
    const int z = blockIdx.z;
    const float* Wt   = Wr + (size_t)z * DIM * DIM;
    const float* bias = (z == 0) ? b0p : (z == 1) ? b1p : b2p;
    float* C          = (z == 0) ? C0  : (z == 1) ? C1  : C2;

    const int tid  = threadIdx.x;
    const int lane = tid & 31;
    const int wid  = tid >> 5;
    const int wm   = (wid >> 1) * 32;
    const int wn   = (wid & 1) * 64;
    const int n0   = blockIdx.x * 128;
    const int m0   = blockIdx.y * 128;

    const int gq = lane >> 2;
    const int tg = lane & 3;

    float acc[2][8][4];
#pragma unroll
    for (int mi = 0; mi < 2; mi++)
#pragma unroll
        for (int ni = 0; ni < 8; ni++)
#pragma unroll
            for (int r = 0; r < 4; r++) acc[mi][ni][r] = 0.f;

#pragma unroll
    for (int kt = 0; kt < NSTG; kt++) {
        load_stage(sb, A, Wt, m0, n0, kt, tid);
        asm volatile("cp.async.commit_group;" ::: "memory");
    }

    for (int kt = 0; kt < NT; kt++) {
        asm volatile("cp.async.wait_group %0;" :: "n"(NSTG - 1) : "memory");
        __syncthreads();

        const float* smf = (const float*)(smem + (kt % NSTG) * STG_BYTES);
        const float* bsf = (const float*)(smem + (kt % NSTG) * STG_BYTES + A_BYTES);

#pragma unroll
        for (int ks = 0; ks < BK; ks += 8) {
            uint32_t afr[2][4];
#pragma unroll
            for (int mi = 0; mi < 2; mi++) {
                int r0 = wm + mi * 16 + gq;
                float2 a0 = *(const float2*)(smf + r0 * 36 + ks + 2 * tg);
                float2 a1 = *(const float2*)(smf + (r0 + 8) * 36 + ks + 2 * tg);
                afr[mi][0] = __float_as_uint(a0.x);
                afr[mi][1] = __float_as_uint(a1.x);
                afr[mi][2] = __float_as_uint(a0.y);
                afr[mi][3] = __float_as_uint(a1.y);
            }
#pragma unroll
            for (int ni = 0; ni < 8; ni++) {
                int nb = wn + ni * 8 + gq;
                float2 bb = *(const float2*)(bsf + nb * 36 + ks + 2 * tg);
                mma8(acc[0][ni], afr[0], __float_as_uint(bb.x), __float_as_uint(bb.y));
                mma8(acc[1][ni], afr[1], __float_as_uint(bb.x), __float_as_uint(bb.y));
            }
        }
        __syncthreads();

        if (kt + NSTG < NT)
            load_stage(sb, A, Wt, m0, n0, kt + NSTG, tid);
        asm volatile("cp.async.commit_group;" ::: "memory");
    }

#pragma unroll
    for (int mi = 0; mi < 2; mi++) {
        int row = m0 + wm + mi * 16 + gq;
#pragma unroll
        for (int ni = 0; ni < 8; ni++) {
            int col = n0 + wn + ni * 8 + 2 * tg;
            float2 bz = *(const float2*)(bias + col);
            float2 v0, v1;
            v0.x = acc[mi][ni][0] + bz.x; v0.y = acc[mi][ni][1] + bz.y;
            v1.x = acc[mi][ni][2] + bz.x; v1.y = acc[mi][ni][3] + bz.y;
            *(float2*)(C + (size_t)row * DIM + col)       = v0;
            *(float2*)(C + (size_t)(row + 8) * DIM + col) = v1;
        }
    }
}

// ---------------- RMSNorm + RoPE ----------------
// grid.y==0: Q in-place, rounded (natural order, feeds flash A-frags)
// grid.y==1: K -> Kp, rounded + k-permuted (feeds flash B-frags via LDS.64)
__global__ __launch_bounds__(256) void rmsnorm_rope2(float* __restrict__ qb,
                                                     float* __restrict__ kb,
                                                     float* __restrict__ kp,
                                                     const float* __restrict__ gqw,
                                                     const float* __restrict__ gkw,
                                                     const float* __restrict__ freqs)
{
    const int t = blockIdx.x;
    const int isk = blockIdx.y;
    float* row = (isk ? kb : qb) + (size_t)t * DIM;
    const float* g = isk ? gkw : gqw;

    float ss = 0.f;
    for (int i = threadIdx.x; i < DIM; i += 256) {
        float v = row[i];
        ss += v * v;
    }
#pragma unroll
    for (int off = 16; off; off >>= 1) ss += __shfl_xor_sync(0xFFFFFFFFu, ss, off);

    __shared__ float red[8];
    __shared__ float stot;
    if ((threadIdx.x & 31) == 0) red[threadIdx.x >> 5] = ss;
    __syncthreads();
    if (threadIdx.x == 0) {
        float tot = 0.f;
#pragma unroll
        for (int i = 0; i < 8; i++) tot += red[i];
        stot = tot;
    }
    __syncthreads();

    const float scale = rsqrtf(stot * (1.f / DIM) + 1e-6f);
    float* krow = kp + (size_t)t * DIM;

    for (int p = threadIdx.x; p < DIM / 2; p += 256) {
        int e   = 2 * p;
        int pin = p & 63;
        float ang = freqs[(size_t)t * 64 + pin];
        float c, s;
        sincosf(ang, &s, &c);
        float x0 = row[e]     * scale * g[e];
        float x1 = row[e + 1] * scale * g[e + 1];
        float y0 = tf32f(x0 * c - x1 * s);
        float y1 = tf32f(x0 * s + x1 * c);
        if (!isk) {
            row[e]     = y0;
            row[e + 1] = y1;
        } else {
            int base = e & ~7;
            int s0 = e & 7, s1 = s0 + 1;
            krow[base + (((s0 & 3) << 1) | (s0 >> 2))] = y0;
            krow[base + (((s1 & 3) << 1) | (s1 >> 2))] = y1;
        }
    }
}

// ---------------- transpose V -> Vt[h][d][t'] with key-permutation + rounding ----------------
__global__ __launch_bounds__(256) void transpose_v(const float* __restrict__ V,
                                                   float* __restrict__ Vt)
{
    __shared__ float t[32][33];
    const int t0 = blockIdx.x * 32;
    const int d0 = blockIdx.y * 32;
    const int tx = threadIdx.x & 31, ty = threadIdx.x >> 5;
#pragma unroll
    for (int i = 0; i < 4; i++)
        t[ty + 8 * i][tx] = V[(size_t)(t0 + ty + 8 * i) * DIM + d0 + tx];
    __syncthreads();
    const int tperm = (tx & ~7) + ((tx & 7) >> 1) + ((tx & 1) << 2);
#pragma unroll
    for (int i = 0; i < 4; i++)
        Vt[(size_t)(d0 + ty + 8 * i) * T_SEQ + t0 + tx] = tf32f(t[tperm][ty + 8 * i]);
}

// ---------------- causal flash attention via mma.sync tf32 ----------------
#define FA_QT  128
#define FA_KT  64
#define Q_LD   132
#define K_LD   136
#define V_LDW  72
#define SM_Q   0
#define SM_KT  (FA_QT * Q_LD)
#define K_BUF  (FA_KT * K_LD)
#define SM_V   (SM_KT + 2 * K_BUF)
#define V_BUF  (HD * V_LDW)
#define FA_SM_FLOATS (SM_V + 2 * V_BUF)
#define FA_SM_BYTES  (FA_SM_FLOATS * 4)

__device__ __forceinline__ void fa_load_kv(uint32_t sb, const float* __restrict__ Kp,
                                           const float* __restrict__ Vt,
                                           int h, int j, int buf, int tid) {
    const int k0 = j * FA_KT;
    uint32_t kbb = sb + (uint32_t)(SM_KT + buf * K_BUF) * 4;
    uint32_t vbb = sb + (uint32_t)(SM_V + buf * V_BUF) * 4;
#pragma unroll
    for (int i = 0; i < 8; i++) {
        int id = tid + i * 256;
        int key = id >> 5, c = id & 31;
        cpa16(kbb + (uint32_t)(key * K_LD + c * 4) * 4,
              Kp + (size_t)(k0 + key) * DIM + h * HD + c * 4);
    }
#pragma unroll
    for (int i = 0; i < 8; i++) {
        int id = tid + i * 256;
        int d = id >> 4, c = id & 15;
        cpa16(vbb + (uint32_t)(d * V_LDW + c * 4) * 4,
              Vt + (size_t)(h * HD + d) * T_SEQ + k0 + c * 4);
    }
}

__global__ __launch_bounds__(256) void flash_mma(const float* __restrict__ Q,
                                                 const float* __restrict__ Kp_g,
                                                 const float* __restrict__ Vt_g,
                                                 float* __restrict__ O)
{
    extern __shared__ float sm[];
    const uint32_t sb = smem_u32(sm);
    const int qt = gridDim.x - 1 - blockIdx.x;
    const int h  = blockIdx.y;
    const int q0 = qt * FA_QT;
    const int tid  = threadIdx.x;
    const int lane = tid & 31, wid = tid >> 5;
    const int gq = lane >> 2, tg = lane & 3;
    const int wrow = wid * 16;
    const int nkt = 2 * qt + 2;
    const float scale = 0.08838834764831845f;

    for (int idx = tid; idx < FA_QT * 32; idx += 256) {
        int r = idx >> 5, c4 = (idx & 31) * 4;
        float4 v = *(const float4*)(Q + (size_t)(q0 + r) * DIM + h * HD + c4);
        float* dst = sm + SM_Q + r * Q_LD + c4;
        dst[0] = v.x; dst[1] = v.y; dst[2] = v.z; dst[3] = v.w;
    }

    fa_load_kv(sb, Kp_g, Vt_g, h, 0, 0, tid);
    asm volatile("cp.async.commit_group;" ::: "memory");
    __syncthreads();

    const float* Qp  = sm + SM_Q + (wrow + gq) * Q_LD;
    const float* Qp8 = Qp + 8 * Q_LD;
    uint32_t qfr[16][4];
#pragma unroll
    for (int ks = 0; ks < 16; ks++) {
        qfr[ks][0] = __float_as_uint(Qp [ks * 8 + tg]);
        qfr[ks][1] = __float_as_uint(Qp8[ks * 8 + tg]);
        qfr[ks][2] = __float_as_uint(Qp [ks * 8 + tg + 4]);
        qfr[ks][3] = __float_as_uint(Qp8[ks * 8 + tg + 4]);
    }

    float oacc[16][4];
#pragma unroll
    for (int nt = 0; nt < 16; nt++)
#pragma unroll
        for (int r = 0; r < 4; r++) oacc[nt][r] = 0.f;

    float m0 = -1e30f, m1 = -1e30f, l0 = 0.f, l1 = 0.f;
    const int r0 = q0 + wrow + gq, r1 = r0 + 8;

    for (int j = 0; j < nkt; j++) {
        if (j + 1 < nkt)
            fa_load_kv(sb, Kp_g, Vt_g, h, j + 1, (j + 1) & 1, tid);
        asm volatile("cp.async.commit_group;" ::: "memory");
        asm volatile("cp.async.wait_group 1;" ::: "memory");
        __syncthreads();

        const int buf = j & 1;
        const int k0 = j * FA_KT;
        const float* Kpb = sm + SM_KT + buf * K_BUF;
        const float* Vpb = sm + SM_V + buf * V_BUF;

        float sacc[8][4];
#pragma unroll
        for (int nt = 0; nt < 8; nt++)
#pragma unroll
            for (int r = 0; r < 4; r++) sacc[nt][r] = 0.f;

#pragma unroll
        for (int ks = 0; ks < 16; ks++) {
#pragma unroll
            for (int nt = 0; nt < 8; nt++) {
                float2 kb = *(const float2*)(Kpb + (nt * 8 + gq) * K_LD + ks * 8 + 2 * tg);
                mma8(sacc[nt], qfr[ks], __float_as_uint(kb.x), __float_as_uint(kb.y));
            }
        }

        const bool diag = (k0 + FA_KT - 1 > q0);
        float mx0 = -1e30f, mx1 = -1e30f;
#pragma unroll
        for (int nt = 0; nt < 8; nt++) {
            int c0 = k0 + nt * 8 + 2 * tg;
            float s0 = sacc[nt][0] * scale, s1 = sacc[nt][1] * scale;
            float s2 = sacc[nt][2] * scale, s3 = sacc[nt][3] * scale;
            if (diag) {
                if (c0     > r0) s0 = -1e30f;
                if (c0 + 1 > r0) s1 = -1e30f;
                if (c0     > r1) s2 = -1e30f;
                if (c0 + 1 > r1) s3 = -1e30f;
            }
            mx0 = fmaxf(mx0, fmaxf(s0, s1));
            mx1 = fmaxf(mx1, fmaxf(s2, s3));
            sacc[nt][0] = s0; sacc[nt][1] = s1; sacc[nt][2] = s2; sacc[nt][3] = s3;
        }
        mx0 = fmaxf(mx0, __shfl_xor_sync(0xFFFFFFFFu, mx0, 1));
        mx0 = fmaxf(mx0, __shfl_xor_sync(0xFFFFFFFFu, mx0, 2));
        mx1 = fmaxf(mx1, __shfl_xor_sync(0xFFFFFFFFu, mx1, 1));
        mx1 = fmaxf(mx1, __shfl_xor_sync(0xFFFFFFFFu, mx1, 2));

        const float mn0 = fmaxf(m0, mx0), mn1 = fmaxf(m1, mx1);
        const float f0 = __expf(m0 - mn0), f1 = __expf(m1 - mn1);
        m0 = mn0; m1 = mn1;

        float rs0 = 0.f, rs1 = 0.f;
#pragma unroll
        for (int nt = 0; nt < 8; nt++) {
            float e0 = __expf(sacc[nt][0] - mn0);
            float e1 = __expf(sacc[nt][1] - mn0);
            float e2 = __expf(sacc[nt][2] - mn1);
            float e3 = __expf(sacc[nt][3] - mn1);
            rs0 += e0 + e1; rs1 += e2 + e3;
            sacc[nt][0] = __uint_as_float(tf32b(e0));
            sacc[nt][1] = __uint_as_float(tf32b(e1));
            sacc[nt][2] = __uint_as_float(tf32b(e2));
            sacc[nt][3] = __uint_as_float(tf32b(e3));
        }
        rs0 += __shfl_xor_sync(0xFFFFFFFFu, rs0, 1);
        rs0 += __shfl_xor_sync(0xFFFFFFFFu, rs0, 2);
        rs1 += __shfl_xor_sync(0xFFFFFFFFu, rs1, 1);
        rs1 += __shfl_xor_sync(0xFFFFFFFFu, rs1, 2);
        l0 = l0 * f0 + rs0;
        l1 = l1 * f1 + rs1;

#pragma unroll
        for (int nt = 0; nt < 16; nt++) {
            oacc[nt][0] *= f0; oacc[nt][1] *= f0;
            oacc[nt][2] *= f1; oacc[nt][3] *= f1;
        }

        const int src0 = (lane & 28) | (tg >> 1);
        const int src2 = src0 + 2;
#pragma unroll
        for (int s = 0; s < 8; s++) {
            float w0 = __shfl_sync(0xFFFFFFFFu, sacc[s][0], src0);
            float w1 = __shfl_sync(0xFFFFFFFFu, sacc[s][1], src0);
            float w2 = __shfl_sync(0xFFFFFFFFu, sacc[s][2], src0);
            float w3 = __shfl_sync(0xFFFFFFFFu, sacc[s][3], src0);
            float w4 = __shfl_sync(0xFFFFFFFFu, sacc[s][0], src2);
            float w5 = __shfl_sync(0xFFFFFFFFu, sacc[s][1], src2);
            float w6 = __shfl_sync(0xFFFFFFFFu, sacc[s][2], src2);
            float w7 = __shfl_sync(0xFFFFFFFFu, sacc[s][3], src2);
            uint32_t af[4];
            af[0] = __float_as_uint((tg & 1) ? w1 : w0);
            af[1] = __float_as_uint((tg & 1) ? w3 : w2);
            af[2] = __float_as_uint((tg & 1) ? w5 : w4);
            af[3] = __float_as_uint((tg & 1) ? w7 : w6);
#pragma unroll
            for (int nt = 0; nt < 16; nt++) {
                float2 vb = *(const float2*)(Vpb + (nt * 8 + gq) * V_LDW + s * 8 + 2 * tg);
                mma8(oacc[nt], af, __float_as_uint(vb.x), __float_as_uint(vb.y));
            }
        }
        __syncthreads();
    }

    // epilogue: write k-PERMUTED + rounded (feeds Wo GEMM A-frags as LDS.64)
    const float inv0 = 1.f / l0, inv1 = 1.f / l1;
    const int d0 = (tg & 1) * 4 + (tg >> 1);   // dest of source col 2tg within 8-group
#pragma unroll
    for (int nt = 0; nt < 16; nt++) {
        int cb = h * HD + nt * 8;
        O[(size_t)r0 * DIM + cb + d0]     = tf32f(oacc[nt][0] * inv0);
        O[(size_t)r0 * DIM + cb + d0 + 2] = tf32f(oacc[nt][1] * inv0);
        O[(size_t)r1 * DIM + cb + d0]     = tf32f(oacc[nt][2] * inv1);
        O[(size_t)r1 * DIM + cb + d0 + 2] = tf32f(oacc[nt][3] * inv1);
    }
}

// ---------------- launch ----------------
extern "C" void kernel_launch(void* const* d_in, const int* in_sizes, int n_in,
                              void* d_out, int out_size)
{
    (void)in_sizes; (void)n_in; (void)out_size;
    const float* x     = (const float*)d_in[0];
    const float* freqs = (const float*)d_in[1];
    const float* Wq    = (const float*)d_in[2];
    const float* bq    = (const float*)d_in[3];
    const float* Wk    = (const float*)d_in[4];
    const float* bk    = (const float*)d_in[5];
    const float* Wv    = (const float*)d_in[6];
    const float* bv    = (const float*)d_in[7];
    const float* Wo    = (const float*)d_in[8];
    const float* bo    = (const float*)d_in[9];
    const float* gq    = (const float*)d_in[10];
    const float* gk    = (const float*)d_in[11];

    float *q, *k, *v, *o, *kp, *vt, *xr, *w;
    cudaGetSymbolAddress((void**)&q,  g_q);
    cudaGetSymbolAddress((void**)&k,  g_k);
    cudaGetSymbolAddress((void**)&v,  g_v);
    cudaGetSymbolAddress((void**)&o,  g_o);
    cudaGetSymbolAddress((void**)&kp, g_kp);
    cudaGetSymbolAddress((void**)&vt, g_vt);
    cudaGetSymbolAddress((void**)&xr, g_xr);
    cudaGetSymbolAddress((void**)&w,  g_w);

    const int gsm = NSTG * STG_BYTES;   // 110592
    cudaFuncSetAttribute(gemm_mma, cudaFuncAttributeMaxDynamicSharedMemorySize, gsm);
    cudaFuncSetAttribute(flash_mma, cudaFuncAttributeMaxDynamicSharedMemorySize, FA_SM_BYTES);

    // pre-passes: x rounded+permuted; weights transposed+permuted+rounded
    permute_k<<<T_SEQ * DIM / 256, 256>>>(x, xr);
    transpose_w<<<dim3(GK / 32, DIM / 32, 4), 256>>>(Wq, Wk, Wv, Wo, w);

    dim3 qkvgrid(DIM / 128, T_SEQ / 128, 3);
    gemm_mma<<<qkvgrid, 256, gsm>>>(xr, w, bq, bk, bv, q, k, v);

    rmsnorm_rope2<<<dim3(T_SEQ, 2), 256>>>(q, k, kp, gq, gk, freqs);

    transpose_v<<<dim3(T_SEQ / 32, DIM / 32), 256>>>(v, vt);

    flash_mma<<<dim3(T_SEQ / FA_QT, NH), 256, FA_SM_BYTES>>>(q, kp, vt, o);

    dim3 ogrid(DIM / 128, T_SEQ / 128, 1);
    gemm_mma<<<ogrid, 256, gsm>>>(o, w + 3 * DIM * DIM, bo, bo, bo,
                                  (float*)d_out, (float*)d_out, (float*)d_out);
}